// round 4
// baseline (speedup 1.0000x reference)
#include <cuda_runtime.h>
#include <cuda_bf16.h>
#include <cstdint>
#include <math.h>

// ---------------- problem dims ----------------
#define NB 64
#define NT 512
#define ND 128
#define NH 512
#define NDS 32
#define NG4 (4 * NH)   // 2048

// ---------------- LSTM kernel config ----------------
#define G 128          // persistent CTAs, 1/SM
#define TPB 256        // 8 warps
#define JPC 4          // hidden units per CTA
#define KTOT 512       // K = NH only (x-projection precomputed)
#define NKS 32         // k-steps of 16
#define ROWB 1024      // bytes per SMEM row (512 bf16)

// SMEM layout (bytes)
#define A_OFF 0                    // [128][1024]  131072
#define B_OFF 131072               // [32][1024]    32768
#define ZB_OFF 163840              // [128][33] f32 16896
#define LSTM_SMEM 180736

__device__ __forceinline__ uint32_t smem_u32(const void* p) {
    uint32_t a;
    asm("{ .reg .u64 t; cvta.to.shared.u64 t, %1; cvt.u32.u64 %0, t; }" : "=r"(a) : "l"(p));
    return a;
}
__device__ __forceinline__ uint16_t bf16_bits(float f) {
    return __bfloat16_as_ushort(__float2bfloat16(f));
}
__device__ __forceinline__ float bf16_val(float f) {
    return __bfloat162float(__float2bfloat16(f));
}
__device__ __forceinline__ uint16_t bf16_lo(float f) {
    return bf16_bits(f - bf16_val(f));
}
__device__ __forceinline__ float sigmoidf_(float x) { return 1.f / (1.f + expf(-x)); }

__device__ __forceinline__ uint4 pack_hi8(float4 a, float4 b) {
    uint4 r;
    r.x = (uint32_t)bf16_bits(a.x) | ((uint32_t)bf16_bits(a.y) << 16);
    r.y = (uint32_t)bf16_bits(a.z) | ((uint32_t)bf16_bits(a.w) << 16);
    r.z = (uint32_t)bf16_bits(b.x) | ((uint32_t)bf16_bits(b.y) << 16);
    r.w = (uint32_t)bf16_bits(b.z) | ((uint32_t)bf16_bits(b.w) << 16);
    return r;
}
__device__ __forceinline__ uint4 pack_lo8(float4 a, float4 b) {
    uint4 r;
    r.x = (uint32_t)bf16_lo(a.x) | ((uint32_t)bf16_lo(a.y) << 16);
    r.y = (uint32_t)bf16_lo(a.z) | ((uint32_t)bf16_lo(a.w) << 16);
    r.z = (uint32_t)bf16_lo(b.x) | ((uint32_t)bf16_lo(b.y) << 16);
    r.w = (uint32_t)bf16_lo(b.z) | ((uint32_t)bf16_lo(b.w) << 16);
    return r;
}

#define LDSM_X4(r0, r1, r2, r3, addr) \
    asm volatile("ldmatrix.sync.aligned.m8n8.x4.shared.b16 {%0,%1,%2,%3}, [%4];" \
        : "=r"(r0), "=r"(r1), "=r"(r2), "=r"(r3) : "r"(addr))

#define MMA_BF16(c, a0, a1, a2, a3, b0, b1) \
    asm volatile("mma.sync.aligned.m16n8k16.row.col.f32.bf16.bf16.f32 " \
        "{%0,%1,%2,%3}, {%4,%5,%6,%7}, {%8,%9}, {%0,%1,%2,%3};" \
        : "+f"((c)[0]), "+f"((c)[1]), "+f"((c)[2]), "+f"((c)[3]) \
        : "r"(a0), "r"(a1), "r"(a2), "r"(a3), "r"(b0), "r"(b1))

// ---------------- global scratch ----------------
__device__ __nv_bfloat16 g_hh[NB][NH];   // h hi
__device__ __nv_bfloat16 g_hl[NB][NH];   // h lo
__device__ float g_xw[NT][NG4][NB];      // x@Wk + bias  (256 MB)
__device__ float g_hs[NT][NH][NB];       // hidden states for dense (64 MB)
__device__ int   g_flags[G];             // per-CTA barrier flags

__global__ void init_kernel() {
    int idx = blockIdx.x * blockDim.x + threadIdx.x;
    if (idx < G) g_flags[idx] = 0;
    uint32_t* ph = reinterpret_cast<uint32_t*>(&g_hh[0][0]);
    uint32_t* pl = reinterpret_cast<uint32_t*>(&g_hl[0][0]);
    for (int i = idx; i < NB * NH / 2; i += gridDim.x * blockDim.x) {
        ph[i] = 0u; pl[i] = 0u;
    }
}

__global__ void nop_kernel() {}

// =====================================================================
// XW kernel: g_xw[t][col][b] = sum_d x[b][t][d]*wk[d][col] + bias[col]
// grid (32 col-chunks of 64, 512 t). bf16 hi/lo split, HMMA.
// A [128 rows: 64 b hi / 64 b lo][K=128], B' [128: 64 col hi / 64 col lo][128]
// =====================================================================
#define XW_ROWB 256
#define XW_B_OFF 32768
#define XW_SMEM 67584     // zb [128][132] f32 aliases A+B after MMA

__global__ void __launch_bounds__(256, 1) xw_kernel(
    const float* __restrict__ x, const float* __restrict__ wk,
    const float* __restrict__ bias)
{
    extern __shared__ char smem[];
    const uint32_t sbu = smem_u32(smem);
    float* zb = reinterpret_cast<float*>(smem);   // alias, used after MMA
    const int tid = threadIdx.x, wid = tid >> 5, lane = tid & 31;
    const int t = blockIdx.y, c0 = blockIdx.x * 64;

    // A: x[b][t][:] -> hi rows 0-63, lo rows 64-127 (16 chunks of 16B per row)
    for (int i = tid; i < 64 * 16; i += 256) {
        int b = i >> 4, cs = i & 15;
        const float4* xp = reinterpret_cast<const float4*>(
            x + ((size_t)b * NT + t) * ND + cs * 8);
        float4 x0 = xp[0], x1 = xp[1];
        *reinterpret_cast<uint4*>(smem + b * XW_ROWB + ((cs ^ (b & 7)) << 4))
            = pack_hi8(x0, x1);
        int rl = b + 64;
        *reinterpret_cast<uint4*>(smem + rl * XW_ROWB + ((cs ^ (rl & 7)) << 4))
            = pack_lo8(x0, x1);
    }
    // B': rows 0-63 hi of col c0+n, 64-127 lo
    for (int i = tid; i < 128 * 128; i += 256) {
        int n = i & 127, k = i >> 7;
        float w = wk[(size_t)k * NG4 + c0 + (n & 63)];
        uint16_t bv = (n < 64) ? bf16_bits(w) : bf16_lo(w);
        *reinterpret_cast<uint16_t*>(smem + XW_B_OFF + n * XW_ROWB +
            ((((k >> 3) ^ (n & 7)) << 4) | ((k & 7) << 1))) = bv;
    }
    __syncthreads();

    const int s7 = lane & 7;
    const int arow = wid * 16 + ((lane >> 3) & 1) * 8 + s7;
    const uint32_t abase = sbu + arow * XW_ROWB;
    const int acb = lane >> 4;
    const int brow = ((lane >> 4) << 3) + s7;
    const int bcb = (lane >> 3) & 1;

    float acc[16][4];
    #pragma unroll
    for (int nt = 0; nt < 16; nt++)
        #pragma unroll
        for (int q = 0; q < 4; q++) acc[nt][q] = 0.f;

    #pragma unroll
    for (int ks = 0; ks < 8; ks++) {
        uint32_t a0, a1, a2, a3;
        LDSM_X4(a0, a1, a2, a3, abase + (((ks * 2 + acb) ^ s7) << 4));
        #pragma unroll
        for (int p = 0; p < 8; p++) {
            uint32_t q0, q1, q2, q3;
            uint32_t baddr = sbu + XW_B_OFF + (p * 16 + brow) * XW_ROWB +
                             (((ks * 2 + bcb) ^ s7) << 4);
            LDSM_X4(q0, q1, q2, q3, baddr);
            MMA_BF16(acc[2 * p],     a0, a1, a2, a3, q0, q1);
            MMA_BF16(acc[2 * p + 1], a0, a1, a2, a3, q2, q3);
        }
    }
    __syncthreads();   // done reading A/B; safe to alias zb

    {
        int r0 = wid * 16 + (lane >> 2);
        int cc = (lane & 3) * 2;
        #pragma unroll
        for (int nt = 0; nt < 16; nt++) {
            int col = nt * 8 + cc;
            zb[r0 * 132 + col]           = acc[nt][0];
            zb[r0 * 132 + col + 1]       = acc[nt][1];
            zb[(r0 + 8) * 132 + col]     = acc[nt][2];
            zb[(r0 + 8) * 132 + col + 1] = acc[nt][3];
        }
    }
    __syncthreads();

    for (int i = tid; i < 64 * 64; i += 256) {
        int b = i & 63, c = i >> 6;
        float z = zb[b * 132 + c] + zb[(b + 64) * 132 + c]
                + zb[b * 132 + c + 64] + zb[(b + 64) * 132 + c + 64]
                + bias[c0 + c];
        g_xw[t][c0 + c][b] = z;
    }
}

// =====================================================================
// Persistent LSTM recurrence, bf16 HMMA hi/lo split, K=512.
// CTA g owns hidden units [4g, 4g+4) -> 16 z-cols -> 32 B' rows.
// =====================================================================
__global__ void __launch_bounds__(TPB, 1) lstm_kernel(
    const float* __restrict__ wr,     // [NH][4H]
    float* __restrict__ out_h, float* __restrict__ out_c)
{
    extern __shared__ char smem[];
    const uint32_t sbu = smem_u32(smem);
    float* zb = reinterpret_cast<float*>(smem + ZB_OFF);   // [128][33]

    const int tid = threadIdx.x;
    const int wid = tid >> 5, lane = tid & 31;
    const int j0 = blockIdx.x * JPC;

    // ---- B' once: rows 0-15 hi of local col, rows 16-31 lo ----
    for (int i = tid; i < 32 * KTOT; i += TPB) {
        int n = i & 31, k = i >> 5;
        int c = n & 15, gate = c >> 2, jj = c & 3;
        float w = wr[(size_t)k * NG4 + gate * NH + j0 + jj];
        uint16_t bv = (n < 16) ? bf16_bits(w) : bf16_lo(w);
        *reinterpret_cast<uint16_t*>(smem + B_OFF + n * ROWB +
            ((((k >> 3) ^ (n & 7)) << 4) | ((k & 7) << 1))) = bv;
    }

    const int gb = tid & 63;
    const int gj = (tid >> 6) & 3;
    float c_state = 0.f;

    const int s7 = lane & 7;
    const int arow = wid * 16 + ((lane >> 3) & 1) * 8 + s7;
    const uint32_t abase = sbu + A_OFF + arow * ROWB;
    const int acb = lane >> 4;
    const int brow = ((lane >> 4) << 3) + s7;
    const uint32_t bbase = sbu + B_OFF + brow * ROWB;
    const int bcb = (lane >> 3) & 1;

    __syncthreads();

    for (int t = 0; t < NT; t++) {
        // prefetch xw (DRAM latency hidden under A build + MMA)
        float xwv[4];
        #pragma unroll
        for (int g = 0; g < 4; g++)
            xwv[g] = __ldcg(&g_xw[t][g * NH + j0 + gj][gb]);

        // ---- A: rows 0-63 = h hi, 64-127 = h lo (64 chunks of 16B/row) ----
        #pragma unroll 8
        for (int cидx = tid; cидx < 128 * 64; cидx += TPB) {
            int row = cидx >> 6, cs = cидx & 63;
            const uint4* src = (row < 64)
                ? reinterpret_cast<const uint4*>(&g_hh[row][0])
                : reinterpret_cast<const uint4*>(&g_hl[row - 64][0]);
            uint4 v = __ldcg(src + cs);
            *reinterpret_cast<uint4*>(smem + row * ROWB +
                ((cs ^ (row & 7)) << 4)) = v;
        }
        __syncthreads();

        // ---- MMA: warp wid owns m-tile [wid*16, +16), 4 n-tiles ----
        float acc[4][4];
        #pragma unroll
        for (int nt = 0; nt < 4; nt++)
            #pragma unroll
            for (int q = 0; q < 4; q++) acc[nt][q] = 0.f;

        #pragma unroll 4
        for (int ks = 0; ks < NKS; ks++) {
            uint32_t a0, a1, a2, a3;
            LDSM_X4(a0, a1, a2, a3, abase + (((ks * 2 + acb) ^ s7) << 4));
            uint32_t b00, b01, b10, b11, b20, b21, b30, b31;
            uint32_t baddr = bbase + (((ks * 2 + bcb) ^ s7) << 4);
            LDSM_X4(b00, b01, b10, b11, baddr);
            LDSM_X4(b20, b21, b30, b31, baddr + 16 * ROWB);
            MMA_BF16(acc[0], a0, a1, a2, a3, b00, b01);
            MMA_BF16(acc[1], a0, a1, a2, a3, b10, b11);
            MMA_BF16(acc[2], a0, a1, a2, a3, b20, b21);
            MMA_BF16(acc[3], a0, a1, a2, a3, b30, b31);
        }

        // ---- epilogue: accums -> zb[128][33] ----
        {
            int r0 = wid * 16 + (lane >> 2);
            int cc = (lane & 3) * 2;
            #pragma unroll
            for (int nt = 0; nt < 4; nt++) {
                int col = nt * 8 + cc;
                zb[r0 * 33 + col]           = acc[nt][0];
                zb[r0 * 33 + col + 1]       = acc[nt][1];
                zb[(r0 + 8) * 33 + col]     = acc[nt][2];
                zb[(r0 + 8) * 33 + col + 1] = acc[nt][3];
            }
        }
        __syncthreads();

        // ---- gates ----
        {
            float z[4];
            #pragma unroll
            for (int g = 0; g < 4; g++) {
                int n = g * 4 + gj;
                z[g] = xwv[g]
                     + zb[gb * 33 + n]      + zb[(gb + 64) * 33 + n]
                     + zb[gb * 33 + n + 16] + zb[(gb + 64) * 33 + n + 16];
            }
            float ig = sigmoidf_(z[0]);
            float fg = sigmoidf_(z[1]);
            float gv = tanhf(z[2]);
            float og = sigmoidf_(z[3]);
            c_state = fg * c_state + ig * gv;
            float hv = og * tanhf(c_state);
            int row = j0 + gj;
            __nv_bfloat16 hh = __float2bfloat16(hv);
            g_hh[gb][row] = hh;
            g_hl[gb][row] = __float2bfloat16(hv - __bfloat162float(hh));
            g_hs[t][row][gb] = hv;
            if (t == NT - 1) {
                out_h[(size_t)gb * NH + row] = hv;
                out_c[(size_t)gb * NH + row] = c_state;
            }
        }
        __syncthreads();

        // ---- contention-free grid barrier: per-CTA flags ----
        if (t < NT - 1) {
            __threadfence();
            if (tid == 0)
                ((volatile int*)g_flags)[blockIdx.x] = t + 1;
            if (tid < 32) {
                const int tgt = t + 1;
                const int* fp = g_flags + lane * 4;
                for (;;) {
                    int f0, f1, f2, f3;
                    asm volatile("ld.volatile.global.v4.s32 {%0,%1,%2,%3}, [%4];"
                        : "=r"(f0), "=r"(f1), "=r"(f2), "=r"(f3) : "l"(fp));
                    bool done = (f0 >= tgt) && (f1 >= tgt) && (f2 >= tgt) && (f3 >= tgt);
                    if (__all_sync(0xffffffffu, done)) break;
                }
                __threadfence();
            }
            __syncthreads();
        }
    }
}

// ---------------- Dense(32, tanh) over all timesteps ----------------
#define DTPB 256
__global__ void __launch_bounds__(DTPB, 1) dense_kernel(
    const float* __restrict__ dw, const float* __restrict__ db,
    float* __restrict__ out)
{
    extern __shared__ float smemf[];
    float* hsm = smemf;
    float* wsm = smemf + NH * NB;
    int t = blockIdx.x, tid = threadIdx.x;
    {
        const float4* src = reinterpret_cast<const float4*>(&g_hs[t][0][0]);
        float4* dst = reinterpret_cast<float4*>(hsm);
        for (int i = tid; i < NH * NB / 4; i += DTPB) dst[i] = src[i];
        const float4* ws = reinterpret_cast<const float4*>(dw);
        float4* wd = reinterpret_cast<float4*>(wsm);
        for (int i = tid; i < NH * NDS / 4; i += DTPB) wd[i] = ws[i];
    }
    __syncthreads();

    int bg = tid & 15, dg = tid >> 4;
    float acc[4][2];
    #pragma unroll
    for (int bi = 0; bi < 4; bi++) { acc[bi][0] = 0.f; acc[bi][1] = 0.f; }
    #pragma unroll 4
    for (int k = 0; k < NH; k++) {
        float4 hv = *reinterpret_cast<const float4*>(&hsm[k * NB + bg * 4]);
        float2 wv = *reinterpret_cast<const float2*>(&wsm[k * NDS + dg * 2]);
        float hvv[4] = {hv.x, hv.y, hv.z, hv.w};
        #pragma unroll
        for (int bi = 0; bi < 4; bi++) {
            acc[bi][0] += hvv[bi] * wv.x;
            acc[bi][1] += hvv[bi] * wv.y;
        }
    }
    float b0 = db[dg * 2], b1 = db[dg * 2 + 1];
    #pragma unroll
    for (int bi = 0; bi < 4; bi++) {
        int b = bg * 4 + bi;
        size_t base = (size_t)b * NT * NDS + (size_t)t * NDS + dg * 2;
        out[base]     = tanhf(acc[bi][0] + b0);
        out[base + 1] = tanhf(acc[bi][1] + b1);
    }
}

#define DENSE_SMEM ((NH * NB + NH * NDS) * 4)

extern "C" void kernel_launch(void* const* d_in, const int* in_sizes, int n_in,
                              void* d_out, int out_size) {
    const float* x    = (const float*)d_in[0];
    const float* wk   = (const float*)d_in[1];
    const float* wr   = (const float*)d_in[2];
    const float* bias = (const float*)d_in[3];
    const float* dw   = (const float*)d_in[4];
    const float* db   = (const float*)d_in[5];
    float* out   = (float*)d_out;
    float* out_h = out + (size_t)NB * NT * NDS;
    float* out_c = out_h + (size_t)NB * NH;

    cudaFuncSetAttribute(xw_kernel,
                         cudaFuncAttributeMaxDynamicSharedMemorySize, XW_SMEM);
    cudaFuncSetAttribute(lstm_kernel,
                         cudaFuncAttributeMaxDynamicSharedMemorySize, LSTM_SMEM);
    cudaFuncSetAttribute(dense_kernel,
                         cudaFuncAttributeMaxDynamicSharedMemorySize, DENSE_SMEM);

    init_kernel<<<64, 256>>>();                                   // launch 0
    xw_kernel<<<dim3(NG4 / 64, NT), 256, XW_SMEM>>>(x, wk, bias); // launch 1
    nop_kernel<<<1, 32>>>();                                      // launch 2
    nop_kernel<<<1, 32>>>();                                      // launch 3
    nop_kernel<<<1, 32>>>();                                      // launch 4
    lstm_kernel<<<G, TPB, LSTM_SMEM>>>(wr, out_h, out_c);         // launch 5 (ncu -s 5)
    dense_kernel<<<NT, DTPB, DENSE_SMEM>>>(dw, db, out);
}

// round 5
// speedup vs baseline: 2.5073x; 2.5073x over previous
#include <cuda_runtime.h>
#include <cuda_bf16.h>
#include <cstdint>
#include <math.h>

// ---------------- problem dims ----------------
#define NB 64
#define NT 512
#define ND 128
#define NH 512
#define NDS 32
#define NG4 (4 * NH)   // 2048

// ---------------- LSTM config ----------------
#define G 128          // persistent CTAs
#define TPB 256        // 8 warps
#define JPC 4          // hidden units per CTA -> 16 true z-cols -> m=32 (hi/lo)
// SMEM layout (bytes)
#define H_OFF 0                    // h' [128 rows][1024B] = 131072
#define ZB_OFF 131072              // zb[2][128][33] f32 = 33792 (aliases W' staging 32KB)
#define LSTM_SMEM 164864

__device__ __forceinline__ uint32_t smem_u32(const void* p) {
    uint32_t a;
    asm("{ .reg .u64 t; cvta.to.shared.u64 t, %1; cvt.u32.u64 %0, t; }" : "=r"(a) : "l"(p));
    return a;
}
__device__ __forceinline__ uint16_t bf16_bits(float f) {
    return __bfloat16_as_ushort(__float2bfloat16(f));
}
__device__ __forceinline__ float bf16_val(float f) {
    return __bfloat162float(__float2bfloat16(f));
}
__device__ __forceinline__ uint16_t bf16_lo(float f) {
    return bf16_bits(f - bf16_val(f));
}
__device__ __forceinline__ float sigmoidf_(float x) { return 1.f / (1.f + expf(-x)); }

__device__ __forceinline__ uint4 pack_hi8(float4 a, float4 b) {
    uint4 r;
    r.x = (uint32_t)bf16_bits(a.x) | ((uint32_t)bf16_bits(a.y) << 16);
    r.y = (uint32_t)bf16_bits(a.z) | ((uint32_t)bf16_bits(a.w) << 16);
    r.z = (uint32_t)bf16_bits(b.x) | ((uint32_t)bf16_bits(b.y) << 16);
    r.w = (uint32_t)bf16_bits(b.z) | ((uint32_t)bf16_bits(b.w) << 16);
    return r;
}
__device__ __forceinline__ uint4 pack_lo8(float4 a, float4 b) {
    uint4 r;
    r.x = (uint32_t)bf16_lo(a.x) | ((uint32_t)bf16_lo(a.y) << 16);
    r.y = (uint32_t)bf16_lo(a.z) | ((uint32_t)bf16_lo(a.w) << 16);
    r.z = (uint32_t)bf16_lo(b.x) | ((uint32_t)bf16_lo(b.y) << 16);
    r.w = (uint32_t)bf16_lo(b.z) | ((uint32_t)bf16_lo(b.w) << 16);
    return r;
}

#define LDSM_X4(r0, r1, r2, r3, addr) \
    asm volatile("ldmatrix.sync.aligned.m8n8.x4.shared.b16 {%0,%1,%2,%3}, [%4];" \
        : "=r"(r0), "=r"(r1), "=r"(r2), "=r"(r3) : "r"(addr))

#define MMA_BF16(c, a0, a1, a2, a3, b0, b1) \
    asm volatile("mma.sync.aligned.m16n8k16.row.col.f32.bf16.bf16.f32 " \
        "{%0,%1,%2,%3}, {%4,%5,%6,%7}, {%8,%9}, {%0,%1,%2,%3};" \
        : "+f"((c)[0]), "+f"((c)[1]), "+f"((c)[2]), "+f"((c)[3]) \
        : "r"(a0), "r"(a1), "r"(a2), "r"(a3), "r"(b0), "r"(b1))

#define CP16(dst, src) \
    asm volatile("cp.async.cg.shared.global [%0], [%1], 16;" :: "r"(dst), "l"(src))
#define CP_COMMIT() asm volatile("cp.async.commit_group;" ::: "memory")
#define CP_WAIT(n)  asm volatile("cp.async.wait_group %0;" :: "n"(n) : "memory")

// ---------------- global scratch ----------------
__device__ __nv_bfloat16 g_hh[NB][NH];          // h hi
__device__ __nv_bfloat16 g_hl[NB][NH];          // h lo
__device__ __nv_bfloat16 g_wt[2 * NG4][ND];     // wk transposed, hi rows 0-2047, lo 2048-4095
__device__ float g_xw[NT][NG4][NB];             // x@Wk + bias
__device__ float g_hs[NT][NH][NB];              // hidden states for dense
__device__ unsigned int g_bar;

__global__ void init_kernel() {
    int idx = blockIdx.x * blockDim.x + threadIdx.x;
    if (idx == 0) g_bar = 0u;
    uint32_t* ph = reinterpret_cast<uint32_t*>(&g_hh[0][0]);
    uint32_t* pl = reinterpret_cast<uint32_t*>(&g_hl[0][0]);
    for (int i = idx; i < NB * NH / 2; i += gridDim.x * blockDim.x) {
        ph[i] = 0u; pl[i] = 0u;
    }
}

// ---- one-time: transpose + bf16 hi/lo split of wk into g_wt ----
__global__ void wbf_kernel(const float* __restrict__ wk) {
    int n = blockIdx.x;          // 0..4095
    int k = threadIdx.x;         // 0..127
    float w = wk[(size_t)k * NG4 + (n & (NG4 - 1))];
    g_wt[n][k] = (n < NG4) ? __ushort_as_bfloat16(bf16_bits(w))
                           : __ushort_as_bfloat16(bf16_lo(w));
}

// =====================================================================
// XW kernel: g_xw[t][col][b] = x[b][t][:] @ wk[:,col] + bias[col]
// grid 512 (one t per CTA). A = x' (m=128 batch hi/lo, k=128) in regs.
// Loop 32 col-blocks of 64: B' tile (128 n-rows = 64 hi + 64 lo) streamed.
// =====================================================================
#define XA_OFF 0           // [128][256B] = 32768
#define XB_OFF 32768       // [128][256B] = 32768
#define XZ_OFF 65536       // zb[2][128][65] f32 = 66560
#define XW_SMEM 132096

__global__ void __launch_bounds__(256, 1) xw_kernel(
    const float* __restrict__ x, const float* __restrict__ bias)
{
    extern __shared__ char smem[];
    const uint32_t sbu = smem_u32(smem);
    float* zb = reinterpret_cast<float*>(smem + XZ_OFF);
    const int tid = threadIdx.x, wid = tid >> 5, lane = tid & 31;
    const int t = blockIdx.x;
    const int s7 = lane & 7;

    // A staging: x' rows 0-63 hi(batch), 64-127 lo
    for (int i = tid; i < 64 * 16; i += 256) {
        int b = i >> 4, cs = i & 15;
        const float4* xp = reinterpret_cast<const float4*>(
            x + ((size_t)b * NT + t) * ND + cs * 8);
        float4 x0 = xp[0], x1 = xp[1];
        *reinterpret_cast<uint4*>(smem + XA_OFF + b * 256 + ((cs ^ (b & 7)) << 4))
            = pack_hi8(x0, x1);
        int rl = b + 64;
        *reinterpret_cast<uint4*>(smem + XA_OFF + rl * 256 + ((cs ^ (rl & 7)) << 4))
            = pack_lo8(x0, x1);
    }
    __syncthreads();

    // a-frags (static): warp mslice = wid&3 owns m-rows [mslice*32, +32)
    const int mslice = wid & 3, whalf = wid >> 2;
    uint32_t ar[8][2][4];
    {
        int row8 = ((lane >> 3) & 1) * 8 + s7;
        int acb = lane >> 4;
        #pragma unroll
        for (int ks = 0; ks < 8; ks++)
            #pragma unroll
            for (int mf = 0; mf < 2; mf++) {
                int row = mslice * 32 + mf * 16 + row8;
                uint32_t addr = sbu + XA_OFF + row * 256 +
                    (((ks * 2 + acb) ^ (row & 7)) << 4);
                LDSM_X4(ar[ks][mf][0], ar[ks][mf][1], ar[ks][mf][2], ar[ks][mf][3], addr);
            }
    }

    const int browl = ((lane >> 4) << 3) + s7;   // b-frag row pattern
    const int bcb = (lane >> 3) & 1;

    for (int cb = 0; cb < 32; cb++) {
        // stream B' tile: rows 0-63 = W_hi cols cb*64.., rows 64-127 = W_lo
        #pragma unroll
        for (int it = 0; it < 8; it++) {
            int i = it * 256 + tid;
            int row = i >> 4, cpi = i & 15;
            const __nv_bfloat16* src = (row < 64)
                ? &g_wt[cb * 64 + row][cpi * 8]
                : &g_wt[NG4 + cb * 64 + (row - 64)][cpi * 8];
            uint32_t dst = sbu + XB_OFF + row * 256 + ((cpi ^ (row & 7)) << 4);
            CP16(dst, src);
        }
        CP_COMMIT();
        CP_WAIT(0);
        __syncthreads();

        float acc[2][8][4];
        #pragma unroll
        for (int mf = 0; mf < 2; mf++)
            #pragma unroll
            for (int nf = 0; nf < 8; nf++)
                #pragma unroll
                for (int q = 0; q < 4; q++) acc[mf][nf][q] = 0.f;

        #pragma unroll
        for (int ks = 0; ks < 8; ks++) {
            #pragma unroll
            for (int q = 0; q < 4; q++) {
                int rowb = whalf * 64 + q * 16 + browl;
                uint32_t baddr = sbu + XB_OFF + rowb * 256 +
                    (((ks * 2 + bcb) ^ s7) << 4);
                uint32_t b0, b1, b2, b3;
                LDSM_X4(b0, b1, b2, b3, baddr);
                #pragma unroll
                for (int mf = 0; mf < 2; mf++) {
                    MMA_BF16(acc[mf][2 * q],     ar[ks][mf][0], ar[ks][mf][1],
                             ar[ks][mf][2], ar[ks][mf][3], b0, b1);
                    MMA_BF16(acc[mf][2 * q + 1], ar[ks][mf][0], ar[ks][mf][1],
                             ar[ks][mf][2], ar[ks][mf][3], b2, b3);
                }
            }
        }

        // epilogue: zb[whalf][m][c]
        #pragma unroll
        for (int mf = 0; mf < 2; mf++)
            #pragma unroll
            for (int nf = 0; nf < 8; nf++) {
                int m = mslice * 32 + mf * 16 + (lane >> 2);
                int c = nf * 8 + 2 * (lane & 3);
                float* zp = zb + (size_t)(whalf * 128 + m) * 65 + c;
                zp[0] = acc[mf][nf][0];
                zp[1] = acc[mf][nf][1];
                zp[8 * 65] = acc[mf][nf][2];
                zp[8 * 65 + 1] = acc[mf][nf][3];
            }
        __syncthreads();

        // reduce 4 partials + bias, write out
        for (int i = tid; i < 64 * 64; i += 256) {
            int b = i & 63, c = i >> 6;
            float z = zb[(size_t)b * 65 + c] + zb[(size_t)(128 + b) * 65 + c]
                    + zb[(size_t)(b + 64) * 65 + c] + zb[(size_t)(128 + b + 64) * 65 + c]
                    + bias[cb * 64 + c];
            g_xw[t][cb * 64 + c][b] = z;
        }
        __syncthreads();
    }
}

// =====================================================================
// Persistent LSTM. Swapped operands: A = W'^T (static regs), B = h'.
// CTA owns 4 hidden units: m=32 (16 true cols x hi/lo), n=128 (64 b x hi/lo),
// k=512. 8 warps = khalf(2, k256 each) x ngrp(4, n32 each).
// =====================================================================
__global__ void __launch_bounds__(TPB, 1) lstm_kernel(
    const float* __restrict__ wr,
    float* __restrict__ out_h, float* __restrict__ out_c)
{
    extern __shared__ char smem[];
    const uint32_t sbu = smem_u32(smem);
    float* zb = reinterpret_cast<float*>(smem + ZB_OFF);   // [2][128][33]

    const int tid = threadIdx.x;
    const int wid = tid >> 5, lane = tid & 31;
    const int j0 = blockIdx.x * JPC;
    const int s7 = lane & 7;
    const int khalf = wid >> 2, ngrp = wid & 3;

    // ---- W'^T staging at ZB_OFF: rows m 0-15 = hi of col (gate*4+jj), 16-31 = lo ----
    for (int i = tid; i < 32 * NH; i += TPB) {
        int m = i & 31, k = i >> 5;
        int c = m & 15, gate = c >> 2, jj = c & 3;
        float w = wr[(size_t)k * NG4 + gate * NH + j0 + jj];
        uint16_t bv = (m < 16) ? bf16_bits(w) : bf16_lo(w);
        *reinterpret_cast<uint16_t*>(smem + ZB_OFF + m * 1024 +
            ((((k >> 3) ^ (m & 7)) << 4) | ((k & 7) << 1))) = bv;
    }
    __syncthreads();

    // ---- a-frags (static, 128 regs): warp's k-range = khalf*256 + ks*16 ----
    uint32_t ar[16][2][4];
    {
        int row8 = ((lane >> 3) & 1) * 8 + s7;
        int acb = lane >> 4;
        #pragma unroll
        for (int ks = 0; ks < 16; ks++)
            #pragma unroll
            for (int mf = 0; mf < 2; mf++) {
                int row = mf * 16 + row8;
                int chunk = khalf * 32 + ks * 2 + acb;
                uint32_t addr = sbu + ZB_OFF + row * 1024 +
                    ((chunk ^ (row & 7)) << 4);
                LDSM_X4(ar[ks][mf][0], ar[ks][mf][1], ar[ks][mf][2], ar[ks][mf][3], addr);
            }
    }
    __syncthreads();   // staging free; zb can be written later

    const int gb = tid & 63;
    const int gj = (tid >> 6) & 3;
    float c_state = 0.f;

    // b-frag lane geometry: rows ngrp*32 + {0,16} + browl
    const int browl = ((lane >> 4) << 3) + s7;
    const int bcb = (lane >> 3) & 1;
    const uint32_t bbase0 = sbu + H_OFF + (ngrp * 32 + browl) * 1024;
    const uint32_t bbase1 = bbase0 + 16 * 1024;

    for (int t = 0; t < NT; t++) {
        // prefetch xw (hidden under h stream)
        float xwv[4];
        #pragma unroll
        for (int g = 0; g < 4; g++)
            xwv[g] = __ldcg(&g_xw[t][g * NH + j0 + gj][gb]);

        // ---- stream h' in 4 k-chunks of 128 via cp.async ----
        #pragma unroll
        for (int ch = 0; ch < 4; ch++) {
            #pragma unroll
            for (int it = 0; it < 8; it++) {
                int i = it * 256 + tid;
                int row = i >> 4, cpi = i & 15;
                const __nv_bfloat16* src = (row < 64)
                    ? &g_hh[row][ch * 128 + cpi * 8]
                    : &g_hl[row - 64][ch * 128 + cpi * 8];
                int gch = ch * 16 + cpi;
                uint32_t dst = sbu + H_OFF + row * 1024 + ((gch ^ (row & 7)) << 4);
                CP16(dst, src);
            }
            CP_COMMIT();
        }

        float acc[2][4][4];
        #pragma unroll
        for (int mf = 0; mf < 2; mf++)
            #pragma unroll
            for (int nf = 0; nf < 4; nf++)
                #pragma unroll
                for (int q = 0; q < 4; q++) acc[mf][nf][q] = 0.f;

        CP_WAIT(2);            // chunks 0,1 landed
        __syncthreads();
        if (khalf == 0) {
            #pragma unroll
            for (int ks = 0; ks < 16; ks++) {
                int chunk = ks * 2 + bcb;
                uint32_t off = ((chunk ^ s7) << 4);
                uint32_t b00, b01, b10, b11, b20, b21, b30, b31;
                LDSM_X4(b00, b01, b10, b11, bbase0 + off);
                LDSM_X4(b20, b21, b30, b31, bbase1 + off);
                #pragma unroll
                for (int mf = 0; mf < 2; mf++) {
                    MMA_BF16(acc[mf][0], ar[ks][mf][0], ar[ks][mf][1], ar[ks][mf][2], ar[ks][mf][3], b00, b01);
                    MMA_BF16(acc[mf][1], ar[ks][mf][0], ar[ks][mf][1], ar[ks][mf][2], ar[ks][mf][3], b10, b11);
                    MMA_BF16(acc[mf][2], ar[ks][mf][0], ar[ks][mf][1], ar[ks][mf][2], ar[ks][mf][3], b20, b21);
                    MMA_BF16(acc[mf][3], ar[ks][mf][0], ar[ks][mf][1], ar[ks][mf][2], ar[ks][mf][3], b30, b31);
                }
            }
        }
        CP_WAIT(0);            // chunks 2,3 landed
        __syncthreads();
        if (khalf == 1) {
            #pragma unroll
            for (int ks = 0; ks < 16; ks++) {
                int chunk = 32 + ks * 2 + bcb;
                uint32_t off = ((chunk ^ s7) << 4);
                uint32_t b00, b01, b10, b11, b20, b21, b30, b31;
                LDSM_X4(b00, b01, b10, b11, bbase0 + off);
                LDSM_X4(b20, b21, b30, b31, bbase1 + off);
                #pragma unroll
                for (int mf = 0; mf < 2; mf++) {
                    MMA_BF16(acc[mf][0], ar[ks][mf][0], ar[ks][mf][1], ar[ks][mf][2], ar[ks][mf][3], b00, b01);
                    MMA_BF16(acc[mf][1], ar[ks][mf][0], ar[ks][mf][1], ar[ks][mf][2], ar[ks][mf][3], b10, b11);
                    MMA_BF16(acc[mf][2], ar[ks][mf][0], ar[ks][mf][1], ar[ks][mf][2], ar[ks][mf][3], b20, b21);
                    MMA_BF16(acc[mf][3], ar[ks][mf][0], ar[ks][mf][1], ar[ks][mf][2], ar[ks][mf][3], b30, b31);
                }
            }
        }
        // epilogue: zb[khalf][n][m]  (n = batch' 0-127, m = col' 0-31)
        #pragma unroll
        for (int mf = 0; mf < 2; mf++)
            #pragma unroll
            for (int nf = 0; nf < 4; nf++) {
                int m = mf * 16 + (lane >> 2);
                int n = ngrp * 32 + nf * 8 + 2 * (lane & 3);
                float* zp = zb + (size_t)(khalf * 128 + n) * 33 + m;
                zp[0]      = acc[mf][nf][0];
                zp[33]     = acc[mf][nf][1];
                zp[8]      = acc[mf][nf][2];
                zp[33 + 8] = acc[mf][nf][3];
            }
        __syncthreads();

        // ---- gates ----
        {
            float z[4];
            #pragma unroll
            for (int g = 0; g < 4; g++) {
                int c = g * 4 + gj;
                float s = xwv[g];
                #pragma unroll
                for (int kh = 0; kh < 2; kh++) {
                    const float* z0 = zb + (size_t)(kh * 128 + gb) * 33;
                    const float* z1 = zb + (size_t)(kh * 128 + gb + 64) * 33;
                    s += z0[c] + z0[c + 16] + z1[c] + z1[c + 16];
                }
                z[g] = s;
            }
            float ig = sigmoidf_(z[0]);
            float fg = sigmoidf_(z[1]);
            float gv = tanhf(z[2]);
            float og = sigmoidf_(z[3]);
            c_state = fg * c_state + ig * gv;
            float hv = og * tanhf(c_state);
            int row = j0 + gj;
            __nv_bfloat16 hh = __float2bfloat16(hv);
            g_hh[gb][row] = hh;
            g_hl[gb][row] = __float2bfloat16(hv - __bfloat162float(hh));
            g_hs[t][row][gb] = hv;
            if (t == NT - 1) {
                out_h[(size_t)gb * NH + row] = hv;
                out_c[(size_t)gb * NH + row] = c_state;
            }
        }
        __syncthreads();

        // ---- grid barrier (monotonic atomic counter; proven in R1/R3) ----
        if (t < NT - 1) {
            if (tid == 0) {
                __threadfence();
                atomicAdd(&g_bar, 1u);
                unsigned int target = (unsigned int)G * (unsigned int)(t + 1);
                unsigned int cur;
                do {
                    asm volatile("ld.volatile.global.u32 %0, [%1];" : "=r"(cur) : "l"(&g_bar));
                } while (cur < target);
                __threadfence();
            }
            __syncthreads();
        }
    }
}

// ---------------- Dense(32, tanh) over all timesteps ----------------
#define DTPB 256
__global__ void __launch_bounds__(DTPB, 1) dense_kernel(
    const float* __restrict__ dw, const float* __restrict__ db,
    float* __restrict__ out)
{
    extern __shared__ float smemf[];
    float* hsm = smemf;
    float* wsm = smemf + NH * NB;
    int t = blockIdx.x, tid = threadIdx.x;
    {
        const float4* src = reinterpret_cast<const float4*>(&g_hs[t][0][0]);
        float4* dst = reinterpret_cast<float4*>(hsm);
        for (int i = tid; i < NH * NB / 4; i += DTPB) dst[i] = src[i];
        const float4* ws = reinterpret_cast<const float4*>(dw);
        float4* wd = reinterpret_cast<float4*>(wsm);
        for (int i = tid; i < NH * NDS / 4; i += DTPB) wd[i] = ws[i];
    }
    __syncthreads();

    int bg = tid & 15, dg = tid >> 4;
    float acc[4][2];
    #pragma unroll
    for (int bi = 0; bi < 4; bi++) { acc[bi][0] = 0.f; acc[bi][1] = 0.f; }
    #pragma unroll 4
    for (int k = 0; k < NH; k++) {
        float4 hv = *reinterpret_cast<const float4*>(&hsm[k * NB + bg * 4]);
        float2 wv = *reinterpret_cast<const float2*>(&wsm[k * NDS + dg * 2]);
        float hvv[4] = {hv.x, hv.y, hv.z, hv.w};
        #pragma unroll
        for (int bi = 0; bi < 4; bi++) {
            acc[bi][0] += hvv[bi] * wv.x;
            acc[bi][1] += hvv[bi] * wv.y;
        }
    }
    float b0 = db[dg * 2], b1 = db[dg * 2 + 1];
    #pragma unroll
    for (int bi = 0; bi < 4; bi++) {
        int b = bg * 4 + bi;
        size_t base = (size_t)b * NT * NDS + (size_t)t * NDS + dg * 2;
        out[base]     = tanhf(acc[bi][0] + b0);
        out[base + 1] = tanhf(acc[bi][1] + b1);
    }
}

#define DENSE_SMEM ((NH * NB + NH * NDS) * 4)

extern "C" void kernel_launch(void* const* d_in, const int* in_sizes, int n_in,
                              void* d_out, int out_size) {
    const float* x    = (const float*)d_in[0];
    const float* wk   = (const float*)d_in[1];
    const float* wr   = (const float*)d_in[2];
    const float* bias = (const float*)d_in[3];
    const float* dw   = (const float*)d_in[4];
    const float* db   = (const float*)d_in[5];
    float* out   = (float*)d_out;
    float* out_h = out + (size_t)NB * NT * NDS;
    float* out_c = out_h + (size_t)NB * NH;

    cudaFuncSetAttribute(xw_kernel,
                         cudaFuncAttributeMaxDynamicSharedMemorySize, XW_SMEM);
    cudaFuncSetAttribute(lstm_kernel,
                         cudaFuncAttributeMaxDynamicSharedMemorySize, LSTM_SMEM);
    cudaFuncSetAttribute(dense_kernel,
                         cudaFuncAttributeMaxDynamicSharedMemorySize, DENSE_SMEM);

    init_kernel<<<64, 256>>>();                          // 0
    wbf_kernel<<<2 * NG4, ND>>>(wk);                     // 1
    xw_kernel<<<NT, 256, XW_SMEM>>>(x, bias);            // 2
    lstm_kernel<<<G, TPB, LSTM_SMEM>>>(wr, out_h, out_c);// 3  <- profiled slot
    dense_kernel<<<NT, DTPB, DENSE_SMEM>>>(dw, db, out); // 4
}